// round 1
// baseline (speedup 1.0000x reference)
#include <cuda_runtime.h>
#include <math.h>

#define BB 2
#define LQ 1024
#define CC 256
#define LK 4096
#define NCH 2
#define NHD 8
#define HD 32
#define EPSV 1e-8f

// ---------------- scratch (device globals; no allocation) ----------------
__device__ float g_partial[BB * 16 * CC];
__device__ float g_smean[BB * CC];
__device__ float g_sproj[BB * CC];
__device__ float g_Qin[BB * LQ * 2 * CC];
__device__ float g_hq[BB * LQ * CC];
__device__ float g_Q[BB * LQ * CC];
__device__ float g_q[BB * LQ * CC];
__device__ float g_k[BB * LK * CC];
__device__ float g_v[BB * LK * CC];
__device__ float g_h[BB * LK * CC];
__device__ float g_att[BB * LQ * CC];
__device__ float g_N[BB * LQ * CC];
__device__ float g_V[BB * LK];

// ---------------- mean of S_SM over Lq ----------------
__global__ void mean_partial_kernel(const float* __restrict__ S_SM) {
    int b = blockIdx.y, seg = blockIdx.x, c = threadIdx.x;
    const float* base = S_SM + ((size_t)b * LQ + (size_t)seg * 64) * CC + c;
    float acc = 0.f;
    #pragma unroll 8
    for (int l = 0; l < 64; l++) acc += base[(size_t)l * CC];
    g_partial[(b * 16 + seg) * CC + c] = acc;
}

__global__ void mean_final_kernel() {
    int i = blockIdx.x * blockDim.x + threadIdx.x;  // 0..511
    int b = i / CC, c = i % CC;
    float acc = 0.f;
    #pragma unroll
    for (int s = 0; s < 16; s++) acc += g_partial[(b * 16 + s) * CC + c];
    g_smean[i] = acc * (1.0f / LQ);
}

// qp_s_proj[b][n] = qp_b1[n] + sum_c smean[b][c] * qp_W1[c][n]   (first C rows)
__global__ void sproj_kernel(const float* __restrict__ qp_W1,
                             const float* __restrict__ qp_b1) {
    int b = blockIdx.x, n = threadIdx.x;
    float acc = qp_b1[n];
    for (int c = 0; c < CC; c++) acc += g_smean[b * CC + c] * qp_W1[(size_t)c * CC + n];
    g_sproj[b * CC + n] = acc;
}

// ---------------- Qin = concat(S_QP, S_SM) ----------------
__global__ void concat_kernel(const float* __restrict__ S_QP,
                              const float* __restrict__ S_SM) {
    int i = blockIdx.x * blockDim.x + threadIdx.x;  // float4 index
    const int row4 = 2 * CC / 4;                    // 128
    const int total = BB * LQ * row4;
    if (i >= total) return;
    int row = i / row4, col4 = i % row4;
    float4 v;
    if (col4 < CC / 4) v = ((const float4*)S_QP)[(size_t)row * (CC / 4) + col4];
    else               v = ((const float4*)S_SM)[(size_t)row * (CC / 4) + col4 - CC / 4];
    ((float4*)g_Qin)[i] = v;
}

// ---------------- generic tiled GEMM ----------------
// C[m,n] = epilogue( sum_k A[m,k]*W[k,n] + bias[n] )
// ATRANS: A stored [K, M] (row-major) -> A[k*lda + m]
// EPI: 0 = bias, 1 = bias+relu, 2 = Dsub - (acc+bias)
template <int EPI, bool ATRANS>
__global__ __launch_bounds__(256)
void gemm_kernel(const float* __restrict__ A, long strideA,
                 const float* __restrict__ W,
                 const float* __restrict__ bias, int biasStride,
                 const float* __restrict__ Dsub,
                 float* __restrict__ Cout, long strideC,
                 int M, int N, int K, int lda) {
    const int BM = 64, BN = 64, BK = 16;
    __shared__ __align__(16) float As[BK][BM];
    __shared__ __align__(16) float Bs[BK][BN];

    int bz = blockIdx.z;
    A += (size_t)bz * strideA;
    Cout += (size_t)bz * strideC;
    const float* biasP = bias + (size_t)bz * biasStride;
    const float* Dp = Dsub ? (Dsub + (size_t)bz * strideC) : nullptr;

    int m0 = blockIdx.x * BM, n0 = blockIdx.y * BN;
    int t = threadIdx.x;
    int tx = t % 16, ty = t / 16;

    float acc[4][4];
    #pragma unroll
    for (int i = 0; i < 4; i++)
        #pragma unroll
        for (int j = 0; j < 4; j++) acc[i][j] = 0.f;

    for (int k0 = 0; k0 < K; k0 += BK) {
        if (ATRANS) {
            int kk = t / 16, mm4 = (t % 16) * 4;
            float4 av = *(const float4*)&A[(size_t)(k0 + kk) * lda + m0 + mm4];
            *(float4*)&As[kk][mm4] = av;
        } else {
            int mm = t / 4, kk4 = (t % 4) * 4;
            float4 av = *(const float4*)&A[(size_t)(m0 + mm) * lda + k0 + kk4];
            As[kk4 + 0][mm] = av.x; As[kk4 + 1][mm] = av.y;
            As[kk4 + 2][mm] = av.z; As[kk4 + 3][mm] = av.w;
        }
        {
            int kk = t / 16, nn4 = (t % 16) * 4;
            *(float4*)&Bs[kk][nn4] = *(const float4*)&W[(size_t)(k0 + kk) * N + n0 + nn4];
        }
        __syncthreads();
        #pragma unroll
        for (int kk = 0; kk < BK; kk++) {
            float4 a4 = *(const float4*)&As[kk][ty * 4];
            float4 b4 = *(const float4*)&Bs[kk][tx * 4];
            float a[4] = {a4.x, a4.y, a4.z, a4.w};
            float b[4] = {b4.x, b4.y, b4.z, b4.w};
            #pragma unroll
            for (int i = 0; i < 4; i++)
                #pragma unroll
                for (int j = 0; j < 4; j++) acc[i][j] += a[i] * b[j];
        }
        __syncthreads();
    }

    #pragma unroll
    for (int i = 0; i < 4; i++) {
        int m = m0 + ty * 4 + i;
        #pragma unroll
        for (int j = 0; j < 4; j++) {
            int n = n0 + tx * 4 + j;
            float v = acc[i][j] + biasP[n];
            if (EPI == 1) v = fmaxf(v, 0.f);
            if (EPI == 2) v = Dp[(size_t)m * N + n] - v;
            Cout[(size_t)m * N + n] = v;
        }
    }
}

// ---------------- P_hat + entropy + V (warp per pixel) ----------------
__device__ __forceinline__ float ent2(float x0, float x1) {
    float d = x0 - x1;
    float p0 = 1.f / (1.f + expf(-d));
    float p1 = 1.f / (1.f + expf(d));
    p0 = fmaxf(p0, EPSV);
    p1 = fmaxf(p1, EPSV);
    return -(p0 * logf(p0) + p1 * logf(p1));
}

__global__ void phat_kernel(const float* __restrict__ P,
                            const float* __restrict__ qp_W2,
                            const float* __restrict__ qp_b2,
                            float* __restrict__ out) {
    int gwarp = (blockIdx.x * blockDim.x + threadIdx.x) >> 5;
    int lane = threadIdx.x & 31;
    if (gwarp >= BB * LK) return;
    int b = gwarp / LK, pix = gwarp % LK;
    const float* hrow = g_h + (size_t)gwarp * CC;
    float a0 = 0.f, a1 = 0.f;
    #pragma unroll
    for (int i = lane; i < CC; i += 32) {
        float hv = hrow[i];
        a0 += hv * qp_W2[i * 2 + 0];
        a1 += hv * qp_W2[i * 2 + 1];
    }
    #pragma unroll
    for (int o = 16; o; o >>= 1) {
        a0 += __shfl_down_sync(0xffffffffu, a0, o);
        a1 += __shfl_down_sync(0xffffffffu, a1, o);
    }
    if (lane == 0) {
        float ph0 = a0 + qp_b2[0];
        float ph1 = a1 + qp_b2[1];
        float* phat = out + (size_t)BB * LQ * CC;
        phat[((size_t)b * NCH + 0) * LK + pix] = ph0;
        phat[((size_t)b * NCH + 1) * LK + pix] = ph1;
        float p0 = P[((size_t)b * NCH + 0) * LK + pix];
        float p1 = P[((size_t)b * NCH + 1) * LK + pix];
        float Vv = ent2(ph0, ph1) - ent2(p0, p1);
        float* vout = out + (size_t)BB * LQ * CC + (size_t)BB * NCH * LK;
        vout[(size_t)b * LK + pix] = Vv;
        g_V[b * LK + pix] = Vv;
    }
}

// ---------------- flash attention with 4-way split-K + merge ----------------
// grid (LQ/32, NH, B); block 128 = 4 chunks x 32 queries
__global__ void attn_kernel(float* __restrict__ attout) {
    __shared__ __align__(16) float Ks[4][32][32];
    __shared__ __align__(16) float Vs[4][32][32];
    __shared__ float bsh[4][32];
    __shared__ float ms[4][32];
    __shared__ float ls[4][32];

    int qt = blockIdx.x, h = blockIdx.y, b = blockIdx.z;
    int t = threadIdx.x;
    int chunk = t >> 5, lane = t & 31;
    int l = qt * 32 + lane;

    const float* qrow = g_q + ((size_t)(b * LQ + l)) * CC + h * HD;
    float qv[32];
    #pragma unroll
    for (int d4 = 0; d4 < 32; d4 += 4) {
        float4 qq = *(const float4*)&qrow[d4];
        qv[d4] = qq.x; qv[d4 + 1] = qq.y; qv[d4 + 2] = qq.z; qv[d4 + 3] = qq.w;
    }

    float m = -1e30f, lsum = 0.f;
    float o[32];
    #pragma unroll
    for (int d = 0; d < 32; d++) o[d] = 0.f;

    const float scale = 0.17677669529663687f;  // 1/sqrt(32)
    int k0base = chunk * (LK / 4);

    for (int kt = 0; kt < LK / 4; kt += 32) {
        int krow = k0base + kt + lane;
        const float* kp = g_k + ((size_t)(b * LK + krow)) * CC + h * HD;
        const float* vp = g_v + ((size_t)(b * LK + krow)) * CC + h * HD;
        #pragma unroll
        for (int d4 = 0; d4 < 32; d4 += 4) {
            *(float4*)&Ks[chunk][lane][d4] = *(const float4*)&kp[d4];
            *(float4*)&Vs[chunk][lane][d4] = *(const float4*)&vp[d4];
        }
        bsh[chunk][lane] = g_V[b * LK + krow];
        __syncwarp();

        float p[32];
        float mt = m;
        #pragma unroll
        for (int j = 0; j < 32; j++) {
            const float4* kr = (const float4*)Ks[chunk][j];
            float s = 0.f;
            #pragma unroll
            for (int d4 = 0; d4 < 8; d4++) {
                float4 kk = kr[d4];
                s += qv[4 * d4 + 0] * kk.x + qv[4 * d4 + 1] * kk.y +
                     qv[4 * d4 + 2] * kk.z + qv[4 * d4 + 3] * kk.w;
            }
            p[j] = s * scale + bsh[chunk][j];
            mt = fmaxf(mt, p[j]);
        }
        float corr = __expf(m - mt);
        lsum *= corr;
        #pragma unroll
        for (int d = 0; d < 32; d++) o[d] *= corr;
        #pragma unroll
        for (int j = 0; j < 32; j++) {
            float e = __expf(p[j] - mt);
            lsum += e;
            const float4* vr = (const float4*)Vs[chunk][j];
            #pragma unroll
            for (int d4 = 0; d4 < 8; d4++) {
                float4 vvv = vr[d4];
                o[4 * d4 + 0] += e * vvv.x;
                o[4 * d4 + 1] += e * vvv.y;
                o[4 * d4 + 2] += e * vvv.z;
                o[4 * d4 + 3] += e * vvv.w;
            }
        }
        m = mt;
        __syncwarp();
    }

    // merge 4 chunks (log-sum-exp)
    __syncthreads();
    ms[chunk][lane] = m;
    __syncthreads();
    float Mg = fmaxf(fmaxf(ms[0][lane], ms[1][lane]), fmaxf(ms[2][lane], ms[3][lane]));
    float f = __expf(m - Mg);
    ls[chunk][lane] = lsum * f;
    float* Os = &Ks[0][0][0];  // overlay Ks (no longer needed)
    float* orow = Os + ((size_t)chunk * 32 + lane) * 32;
    #pragma unroll
    for (int d = 0; d < 32; d++) orow[d] = o[d] * f;
    __syncthreads();
    if (chunk == 0) {
        float L = ls[0][lane] + ls[1][lane] + ls[2][lane] + ls[3][lane];
        float inv = 1.f / L;
        float* dst = attout + ((size_t)(b * LQ + l)) * CC + h * HD;
        #pragma unroll
        for (int d = 0; d < 32; d++) {
            float s = Os[((size_t)0 * 32 + lane) * 32 + d] +
                      Os[((size_t)1 * 32 + lane) * 32 + d] +
                      Os[((size_t)2 * 32 + lane) * 32 + d] +
                      Os[((size_t)3 * 32 + lane) * 32 + d];
            dst[d] = s * inv;
        }
    }
}

// ---------------- launch ----------------
extern "C" void kernel_launch(void* const* d_in, const int* in_sizes, int n_in,
                              void* d_out, int out_size) {
    const float* S_QP   = (const float*)d_in[0];
    const float* S_SM   = (const float*)d_in[1];
    const float* f_q    = (const float*)d_in[2];
    const float* P      = (const float*)d_in[3];
    const float* qp_W1  = (const float*)d_in[4];
    const float* qp_b1  = (const float*)d_in[5];
    const float* qp_W2  = (const float*)d_in[6];
    const float* qp_b2  = (const float*)d_in[7];
    const float* phiQ_W1 = (const float*)d_in[8];
    const float* phiQ_b1 = (const float*)d_in[9];
    const float* phiQ_W2 = (const float*)d_in[10];
    const float* phiQ_b2 = (const float*)d_in[11];
    const float* Wq = (const float*)d_in[12];
    const float* bq = (const float*)d_in[13];
    const float* Wk = (const float*)d_in[14];
    const float* bk = (const float*)d_in[15];
    const float* Wv = (const float*)d_in[16];
    const float* bv = (const float*)d_in[17];
    const float* Wo = (const float*)d_in[18];
    const float* bo = (const float*)d_in[19];
    const float* phi_W = (const float*)d_in[20];
    const float* phi_b = (const float*)d_in[21];
    float* out = (float*)d_out;

    float *p_Qin, *p_hq, *p_Q, *p_q, *p_k, *p_v, *p_h, *p_att, *p_N, *p_sproj;
    cudaGetSymbolAddress((void**)&p_Qin, g_Qin);
    cudaGetSymbolAddress((void**)&p_hq, g_hq);
    cudaGetSymbolAddress((void**)&p_Q, g_Q);
    cudaGetSymbolAddress((void**)&p_q, g_q);
    cudaGetSymbolAddress((void**)&p_k, g_k);
    cudaGetSymbolAddress((void**)&p_v, g_v);
    cudaGetSymbolAddress((void**)&p_h, g_h);
    cudaGetSymbolAddress((void**)&p_att, g_att);
    cudaGetSymbolAddress((void**)&p_N, g_N);
    cudaGetSymbolAddress((void**)&p_sproj, g_sproj);

    // 1-3: prototype mean + folded s-projection bias
    mean_partial_kernel<<<dim3(16, BB), 256>>>(S_SM);
    mean_final_kernel<<<2, 256>>>();
    sproj_kernel<<<BB, 256>>>(qp_W1, qp_b1);

    // 4: Qin concat
    {
        int total4 = BB * LQ * 2 * CC / 4;
        concat_kernel<<<(total4 + 255) / 256, 256>>>(S_QP, S_SM);
    }

    // 5: hq = relu(Qin @ phiQ_W1 + b1)   [2048,512]x[512,256]
    gemm_kernel<1, false><<<dim3(32, 4, 1), 256>>>(
        p_Qin, 0, phiQ_W1, phiQ_b1, 0, nullptr, p_hq, 0, 2048, 256, 512, 512);
    // 6: Q = hq @ phiQ_W2 + b2
    gemm_kernel<0, false><<<dim3(32, 4, 1), 256>>>(
        p_hq, 0, phiQ_W2, phiQ_b2, 0, nullptr, p_Q, 0, 2048, 256, 256, 256);
    // 7: q = Q @ Wq + bq
    gemm_kernel<0, false><<<dim3(32, 4, 1), 256>>>(
        p_Q, 0, Wq, bq, 0, nullptr, p_q, 0, 2048, 256, 256, 256);
    // 8: k = f_q^T @ Wk + bk  (A trans, per-batch)
    gemm_kernel<0, true><<<dim3(64, 4, BB), 256>>>(
        f_q, (long)CC * LK, Wk, bk, 0, nullptr, p_k, (long)LK * CC, 4096, 256, 256, LK);
    // 9: v = f_q^T @ Wv + bv
    gemm_kernel<0, true><<<dim3(64, 4, BB), 256>>>(
        f_q, (long)CC * LK, Wv, bv, 0, nullptr, p_v, (long)LK * CC, 4096, 256, 256, LK);
    // 10: h = relu(f_q^T @ qp_W1[C:] + sproj[b])
    gemm_kernel<1, true><<<dim3(64, 4, BB), 256>>>(
        f_q, (long)CC * LK, qp_W1 + (size_t)CC * CC, p_sproj, CC, nullptr,
        p_h, (long)LK * CC, 4096, 256, 256, LK);

    // 11: P_hat + entropy + V
    phat_kernel<<<(BB * LK) / 8, 256>>>(P, qp_W2, qp_b2, out);

    // 12: attention
    attn_kernel<<<dim3(LQ / 32, NHD, BB), 128>>>(p_att);

    // 13: N = att @ Wo + bo
    gemm_kernel<0, false><<<dim3(32, 4, 1), 256>>>(
        p_att, 0, Wo, bo, 0, nullptr, p_N, 0, 2048, 256, 256, 256);
    // 14: S_IC = S_SM - (N @ phi_W + phi_b)
    gemm_kernel<2, false><<<dim3(32, 4, 1), 256>>>(
        p_N, 0, phi_W, phi_b, 0, S_SM, out, 0, 2048, 256, 256, 256);
}

// round 2
// speedup vs baseline: 2.6505x; 2.6505x over previous
#include <cuda_runtime.h>
#include <cuda_bf16.h>
#include <math.h>

#define BB 2
#define LQ 1024
#define CC 256
#define LK 4096
#define NCH 2
#define NHD 8
#define HD 32
#define EPSV 1e-8f

// ---------------- scratch (device globals; no allocation) ----------------
__device__ float g_partial[BB * 16 * CC];
__device__ float g_smean[BB * CC];
__device__ float g_sproj[BB * CC];
__device__ float g_Qin[BB * LQ * 2 * CC];
__device__ float g_hq[BB * LQ * CC];
__device__ float g_Q[BB * LQ * CC];
__device__ float g_h[BB * LK * CC];
__device__ float g_att[BB * LQ * CC];
__device__ float g_N[BB * LQ * CC];
__device__ float g_V[BB * LK];
__device__ __nv_bfloat16 g_qb[BB * LQ * CC];   // q (scaled), bf16 row-major
__device__ __nv_bfloat16 g_kb[BB * LK * CC];   // k, bf16 row-major
__device__ __nv_bfloat16 g_vT[BB * CC * LK];   // v, bf16 TRANSPOSED [b][C][Lk]

// ---------------- mean of S_SM over Lq ----------------
__global__ void mean_partial_kernel(const float* __restrict__ S_SM) {
    int b = blockIdx.y, seg = blockIdx.x, c = threadIdx.x;
    const float* base = S_SM + ((size_t)b * LQ + (size_t)seg * 64) * CC + c;
    float acc = 0.f;
    #pragma unroll 8
    for (int l = 0; l < 64; l++) acc += base[(size_t)l * CC];
    g_partial[(b * 16 + seg) * CC + c] = acc;
}

__global__ void mean_final_kernel() {
    int i = blockIdx.x * blockDim.x + threadIdx.x;  // 0..511
    int b = i / CC, c = i % CC;
    float acc = 0.f;
    #pragma unroll
    for (int s = 0; s < 16; s++) acc += g_partial[(b * 16 + s) * CC + c];
    g_smean[i] = acc * (1.0f / LQ);
}

__global__ void sproj_kernel(const float* __restrict__ qp_W1,
                             const float* __restrict__ qp_b1) {
    int b = blockIdx.x, n = threadIdx.x;
    float acc = qp_b1[n];
    for (int c = 0; c < CC; c++) acc += g_smean[b * CC + c] * qp_W1[(size_t)c * CC + n];
    g_sproj[b * CC + n] = acc;
}

// ---------------- Qin = concat(S_QP, S_SM) ----------------
__global__ void concat_kernel(const float* __restrict__ S_QP,
                              const float* __restrict__ S_SM) {
    int i = blockIdx.x * blockDim.x + threadIdx.x;
    const int row4 = 2 * CC / 4;
    const int total = BB * LQ * row4;
    if (i >= total) return;
    int row = i / row4, col4 = i % row4;
    float4 v;
    if (col4 < CC / 4) v = ((const float4*)S_QP)[(size_t)row * (CC / 4) + col4];
    else               v = ((const float4*)S_SM)[(size_t)row * (CC / 4) + col4 - CC / 4];
    ((float4*)g_Qin)[i] = v;
}

// ---------------- generic tiled GEMM ----------------
// EPI: 0 = bias, 1 = bias+relu, 2 = Dsub - (acc+bias)
// OUTMODE: 0 = fp32 row-major, 1 = bf16 row-major (*outScale), 2 = bf16 transposed [N][M]
template <int EPI, bool ATRANS, int OUTMODE>
__global__ __launch_bounds__(256)
void gemm_kernel(const float* __restrict__ A, long strideA,
                 const float* __restrict__ W,
                 const float* __restrict__ bias, int biasStride,
                 const float* __restrict__ Dsub,
                 float* __restrict__ CoutF, __nv_bfloat16* __restrict__ CoutB,
                 long strideC, float outScale,
                 int M, int N, int K, int lda) {
    const int BM = 64, BN = 64, BK = 16;
    __shared__ __align__(16) float As[BK][BM];
    __shared__ __align__(16) float Bs[BK][BN];

    int bz = blockIdx.z;
    A += (size_t)bz * strideA;
    if (OUTMODE == 0) CoutF += (size_t)bz * strideC;
    else              CoutB += (size_t)bz * strideC;
    const float* biasP = bias + (size_t)bz * biasStride;
    const float* Dp = Dsub ? (Dsub + (size_t)bz * strideC) : nullptr;

    int m0 = blockIdx.x * BM, n0 = blockIdx.y * BN;
    int t = threadIdx.x;
    int tx = t % 16, ty = t / 16;

    float acc[4][4];
    #pragma unroll
    for (int i = 0; i < 4; i++)
        #pragma unroll
        for (int j = 0; j < 4; j++) acc[i][j] = 0.f;

    for (int k0 = 0; k0 < K; k0 += BK) {
        if (ATRANS) {
            int kk = t / 16, mm4 = (t % 16) * 4;
            float4 av = *(const float4*)&A[(size_t)(k0 + kk) * lda + m0 + mm4];
            *(float4*)&As[kk][mm4] = av;
        } else {
            int mm = t / 4, kk4 = (t % 4) * 4;
            float4 av = *(const float4*)&A[(size_t)(m0 + mm) * lda + k0 + kk4];
            As[kk4 + 0][mm] = av.x; As[kk4 + 1][mm] = av.y;
            As[kk4 + 2][mm] = av.z; As[kk4 + 3][mm] = av.w;
        }
        {
            int kk = t / 16, nn4 = (t % 16) * 4;
            *(float4*)&Bs[kk][nn4] = *(const float4*)&W[(size_t)(k0 + kk) * N + n0 + nn4];
        }
        __syncthreads();
        #pragma unroll
        for (int kk = 0; kk < BK; kk++) {
            float4 a4 = *(const float4*)&As[kk][ty * 4];
            float4 b4 = *(const float4*)&Bs[kk][tx * 4];
            float a[4] = {a4.x, a4.y, a4.z, a4.w};
            float b[4] = {b4.x, b4.y, b4.z, b4.w};
            #pragma unroll
            for (int i = 0; i < 4; i++)
                #pragma unroll
                for (int j = 0; j < 4; j++) acc[i][j] += a[i] * b[j];
        }
        __syncthreads();
    }

    #pragma unroll
    for (int i = 0; i < 4; i++) {
        int m = m0 + ty * 4 + i;
        #pragma unroll
        for (int j = 0; j < 4; j++) {
            int n = n0 + tx * 4 + j;
            float v = acc[i][j] + biasP[n];
            if (EPI == 1) v = fmaxf(v, 0.f);
            if (EPI == 2) v = Dp[(size_t)m * N + n] - v;
            if (OUTMODE == 0) CoutF[(size_t)m * N + n] = v;
            else if (OUTMODE == 1) CoutB[(size_t)m * N + n] = __float2bfloat16_rn(v * outScale);
            else CoutB[(size_t)n * M + m] = __float2bfloat16_rn(v);
        }
    }
}

// ---------------- P_hat + entropy + V (warp per pixel) ----------------
__device__ __forceinline__ float ent2(float x0, float x1) {
    float d = x0 - x1;
    float p0 = 1.f / (1.f + expf(-d));
    float p1 = 1.f / (1.f + expf(d));
    p0 = fmaxf(p0, EPSV);
    p1 = fmaxf(p1, EPSV);
    return -(p0 * logf(p0) + p1 * logf(p1));
}

__global__ void phat_kernel(const float* __restrict__ P,
                            const float* __restrict__ qp_W2,
                            const float* __restrict__ qp_b2,
                            float* __restrict__ out) {
    int gwarp = (blockIdx.x * blockDim.x + threadIdx.x) >> 5;
    int lane = threadIdx.x & 31;
    if (gwarp >= BB * LK) return;
    int b = gwarp / LK, pix = gwarp % LK;
    const float* hrow = g_h + (size_t)gwarp * CC;
    float a0 = 0.f, a1 = 0.f;
    #pragma unroll
    for (int i = lane; i < CC; i += 32) {
        float hv = hrow[i];
        a0 += hv * qp_W2[i * 2 + 0];
        a1 += hv * qp_W2[i * 2 + 1];
    }
    #pragma unroll
    for (int o = 16; o; o >>= 1) {
        a0 += __shfl_down_sync(0xffffffffu, a0, o);
        a1 += __shfl_down_sync(0xffffffffu, a1, o);
    }
    if (lane == 0) {
        float ph0 = a0 + qp_b2[0];
        float ph1 = a1 + qp_b2[1];
        float* phat = out + (size_t)BB * LQ * CC;
        phat[((size_t)b * NCH + 0) * LK + pix] = ph0;
        phat[((size_t)b * NCH + 1) * LK + pix] = ph1;
        float p0 = P[((size_t)b * NCH + 0) * LK + pix];
        float p1 = P[((size_t)b * NCH + 1) * LK + pix];
        float Vv = ent2(ph0, ph1) - ent2(p0, p1);
        float* vout = out + (size_t)BB * LQ * CC + (size_t)BB * NCH * LK;
        vout[(size_t)b * LK + pix] = Vv;
        g_V[b * LK + pix] = Vv;
    }
}

// ---------------- bf16 tensor-core attention ----------------
__device__ __forceinline__ void mma16816(float* c, const unsigned* a, const unsigned* b) {
    asm volatile(
        "mma.sync.aligned.m16n8k16.row.col.f32.bf16.bf16.f32 "
        "{%0,%1,%2,%3}, {%4,%5,%6,%7}, {%8,%9}, {%0,%1,%2,%3};\n"
        : "+f"(c[0]), "+f"(c[1]), "+f"(c[2]), "+f"(c[3])
        : "r"(a[0]), "r"(a[1]), "r"(a[2]), "r"(a[3]), "r"(b[0]), "r"(b[1]));
}

__device__ __forceinline__ unsigned packbf(float x, float y) {
    __nv_bfloat162 h = __floats2bfloat162_rn(x, y);
    return *(unsigned*)&h;
}

// grid (LQ/64, NH, B), block 128 (4 warps x 16 query rows each)
// Logits are bounded (|q.k*scale| < ~0.1, |V| <= ln2), so exp without
// max-subtraction is numerically safe and mathematically exact.
__global__ __launch_bounds__(128)
void attn_mma_kernel(const __nv_bfloat16* __restrict__ qb,
                     const __nv_bfloat16* __restrict__ kb,
                     const __nv_bfloat16* __restrict__ vT,
                     float* __restrict__ attout) {
    __shared__ __align__(16) __nv_bfloat16 Ks[64][40];   // keys x dims (padded)
    __shared__ __align__(16) __nv_bfloat16 Vt[32][72];   // dims x keys (padded)
    __shared__ float bias_s[64];

    int qt = blockIdx.x, h = blockIdx.y, b = blockIdx.z;
    int tid = threadIdx.x, warp = tid >> 5, lane = tid & 31;
    int qr = qt * 64 + warp * 16 + (lane >> 2);
    int qc = (lane & 3) * 2;

    // Q A-fragments straight from gmem (2 k-steps of 16)
    unsigned aq[2][4];
    const __nv_bfloat16* qbase = qb + ((size_t)(b * LQ) + qr) * CC + h * HD;
    #pragma unroll
    for (int ks = 0; ks < 2; ks++) {
        aq[ks][0] = *(const unsigned*)(qbase + ks * 16 + qc);
        aq[ks][1] = *(const unsigned*)(qbase + (size_t)8 * CC + ks * 16 + qc);
        aq[ks][2] = *(const unsigned*)(qbase + ks * 16 + qc + 8);
        aq[ks][3] = *(const unsigned*)(qbase + (size_t)8 * CC + ks * 16 + qc + 8);
    }

    float o[4][4];
    #pragma unroll
    for (int i = 0; i < 4; i++)
        #pragma unroll
        for (int j = 0; j < 4; j++) o[i][j] = 0.f;
    float l0 = 0.f, l1 = 0.f;

    for (int kb0 = 0; kb0 < LK; kb0 += 64) {
        __syncthreads();
        // load K tile [64 keys][32 dims]
        #pragma unroll
        for (int it = 0; it < 4; it++) {
            int i = tid + it * 128;
            int row = i >> 3, j = i & 7;
            *(uint2*)&Ks[row][j * 4] =
                *(const uint2*)(kb + ((size_t)(b * LK) + kb0 + row) * CC + h * HD + j * 4);
        }
        // load V tile transposed [32 dims][64 keys] (vT already dim-major)
        #pragma unroll
        for (int it = 0; it < 4; it++) {
            int i = tid + it * 128;
            int row = i >> 4, j = i & 15;
            *(uint2*)&Vt[row][j * 4] =
                *(const uint2*)(vT + ((size_t)b * CC + h * HD + row) * LK + kb0 + j * 4);
        }
        if (tid < 64) bias_s[tid] = g_V[b * LK + kb0 + tid];
        __syncthreads();

        // S = q @ K^T  (scale already folded into q)
        float c[8][4];
        #pragma unroll
        for (int nt = 0; nt < 8; nt++) {
            c[nt][0] = c[nt][1] = c[nt][2] = c[nt][3] = 0.f;
            int n = nt * 8 + (lane >> 2);
            #pragma unroll
            for (int ks = 0; ks < 2; ks++) {
                unsigned bf[2];
                int k0 = ks * 16 + qc;
                bf[0] = *(const unsigned*)&Ks[n][k0];
                bf[1] = *(const unsigned*)&Ks[n][k0 + 8];
                mma16816(c[nt], aq[ks], bf);
            }
        }
        // p = exp(s + bias); accumulate row sums
        #pragma unroll
        for (int nt = 0; nt < 8; nt++) {
            float b0 = bias_s[nt * 8 + qc], b1 = bias_s[nt * 8 + qc + 1];
            c[nt][0] = __expf(c[nt][0] + b0);
            c[nt][1] = __expf(c[nt][1] + b1);
            c[nt][2] = __expf(c[nt][2] + b0);
            c[nt][3] = __expf(c[nt][3] + b1);
            l0 += c[nt][0] + c[nt][1];
            l1 += c[nt][2] + c[nt][3];
        }
        // O += P @ V
        #pragma unroll
        for (int ks2 = 0; ks2 < 4; ks2++) {
            unsigned ap[4];
            ap[0] = packbf(c[2 * ks2][0], c[2 * ks2][1]);
            ap[1] = packbf(c[2 * ks2][2], c[2 * ks2][3]);
            ap[2] = packbf(c[2 * ks2 + 1][0], c[2 * ks2 + 1][1]);
            ap[3] = packbf(c[2 * ks2 + 1][2], c[2 * ks2 + 1][3]);
            #pragma unroll
            for (int nt2 = 0; nt2 < 4; nt2++) {
                int d = nt2 * 8 + (lane >> 2);
                int k0 = ks2 * 16 + qc;
                unsigned bf[2];
                bf[0] = *(const unsigned*)&Vt[d][k0];
                bf[1] = *(const unsigned*)&Vt[d][k0 + 8];
                mma16816(o[nt2], ap, bf);
            }
        }
    }

    // reduce row sums across quad
    l0 += __shfl_xor_sync(0xffffffffu, l0, 1);
    l0 += __shfl_xor_sync(0xffffffffu, l0, 2);
    l1 += __shfl_xor_sync(0xffffffffu, l1, 1);
    l1 += __shfl_xor_sync(0xffffffffu, l1, 2);
    float inv0 = 1.f / l0, inv1 = 1.f / l1;

    float* dst = attout + ((size_t)(b * LQ) + qr) * CC + h * HD;
    #pragma unroll
    for (int nt2 = 0; nt2 < 4; nt2++) {
        int c0 = nt2 * 8 + qc;
        float2 v0 = make_float2(o[nt2][0] * inv0, o[nt2][1] * inv0);
        float2 v1 = make_float2(o[nt2][2] * inv1, o[nt2][3] * inv1);
        *(float2*)&dst[c0] = v0;
        *(float2*)&dst[(size_t)8 * CC + c0] = v1;
    }
}

// ---------------- launch ----------------
extern "C" void kernel_launch(void* const* d_in, const int* in_sizes, int n_in,
                              void* d_out, int out_size) {
    const float* S_QP   = (const float*)d_in[0];
    const float* S_SM   = (const float*)d_in[1];
    const float* f_q    = (const float*)d_in[2];
    const float* P      = (const float*)d_in[3];
    const float* qp_W1  = (const float*)d_in[4];
    const float* qp_b1  = (const float*)d_in[5];
    const float* qp_W2  = (const float*)d_in[6];
    const float* qp_b2  = (const float*)d_in[7];
    const float* phiQ_W1 = (const float*)d_in[8];
    const float* phiQ_b1 = (const float*)d_in[9];
    const float* phiQ_W2 = (const float*)d_in[10];
    const float* phiQ_b2 = (const float*)d_in[11];
    const float* Wq = (const float*)d_in[12];
    const float* bq = (const float*)d_in[13];
    const float* Wk = (const float*)d_in[14];
    const float* bk = (const float*)d_in[15];
    const float* Wv = (const float*)d_in[16];
    const float* bv = (const float*)d_in[17];
    const float* Wo = (const float*)d_in[18];
    const float* bo = (const float*)d_in[19];
    const float* phi_W = (const float*)d_in[20];
    const float* phi_b = (const float*)d_in[21];
    float* out = (float*)d_out;

    float *p_Qin, *p_hq, *p_Q, *p_h, *p_att, *p_N, *p_sproj;
    __nv_bfloat16 *p_qb, *p_kb, *p_vT;
    cudaGetSymbolAddress((void**)&p_Qin, g_Qin);
    cudaGetSymbolAddress((void**)&p_hq, g_hq);
    cudaGetSymbolAddress((void**)&p_Q, g_Q);
    cudaGetSymbolAddress((void**)&p_h, g_h);
    cudaGetSymbolAddress((void**)&p_att, g_att);
    cudaGetSymbolAddress((void**)&p_N, g_N);
    cudaGetSymbolAddress((void**)&p_sproj, g_sproj);
    cudaGetSymbolAddress((void**)&p_qb, g_qb);
    cudaGetSymbolAddress((void**)&p_kb, g_kb);
    cudaGetSymbolAddress((void**)&p_vT, g_vT);

    const float attnScale = 0.17677669529663687f;  // 1/sqrt(32)

    mean_partial_kernel<<<dim3(16, BB), 256>>>(S_SM);
    mean_final_kernel<<<2, 256>>>();
    sproj_kernel<<<BB, 256>>>(qp_W1, qp_b1);

    {
        int total4 = BB * LQ * 2 * CC / 4;
        concat_kernel<<<(total4 + 255) / 256, 256>>>(S_QP, S_SM);
    }

    // hq = relu(Qin @ phiQ_W1 + b1)
    gemm_kernel<1, false, 0><<<dim3(32, 4, 1), 256>>>(
        p_Qin, 0, phiQ_W1, phiQ_b1, 0, nullptr, p_hq, nullptr, 0, 1.f, 2048, 256, 512, 512);
    // Q = hq @ phiQ_W2 + b2
    gemm_kernel<0, false, 0><<<dim3(32, 4, 1), 256>>>(
        p_hq, 0, phiQ_W2, phiQ_b2, 0, nullptr, p_Q, nullptr, 0, 1.f, 2048, 256, 256, 256);
    // q = (Q @ Wq + bq) * scale -> bf16
    gemm_kernel<0, false, 1><<<dim3(32, 4, 1), 256>>>(
        p_Q, 0, Wq, bq, 0, nullptr, nullptr, p_qb, 0, attnScale, 2048, 256, 256, 256);
    // k = f_q^T @ Wk + bk -> bf16
    gemm_kernel<0, true, 1><<<dim3(64, 4, BB), 256>>>(
        f_q, (long)CC * LK, Wk, bk, 0, nullptr, nullptr, p_kb, (long)LK * CC, 1.f,
        4096, 256, 256, LK);
    // v = f_q^T @ Wv + bv -> bf16 transposed [C][Lk]
    gemm_kernel<0, true, 2><<<dim3(64, 4, BB), 256>>>(
        f_q, (long)CC * LK, Wv, bv, 0, nullptr, nullptr, p_vT, (long)CC * LK, 1.f,
        4096, 256, 256, LK);
    // h = relu(f_q^T @ qp_W1[C:] + sproj[b])  (fp32: feeds P_hat output)
    gemm_kernel<1, true, 0><<<dim3(64, 4, BB), 256>>>(
        f_q, (long)CC * LK, qp_W1 + (size_t)CC * CC, p_sproj, CC, nullptr,
        p_h, nullptr, (long)LK * CC, 1.f, 4096, 256, 256, LK);

    // P_hat + entropy + V
    phat_kernel<<<(BB * LK) / 8, 256>>>(P, qp_W2, qp_b2, out);

    // attention (bf16 HMMA)
    attn_mma_kernel<<<dim3(LQ / 64, NHD, BB), 128>>>(p_qb, p_kb, p_vT, p_att);

    // N = att @ Wo + bo
    gemm_kernel<0, false, 0><<<dim3(32, 4, 1), 256>>>(
        p_att, 0, Wo, bo, 0, nullptr, p_N, nullptr, 0, 1.f, 2048, 256, 256, 256);
    // S_IC = S_SM - (N @ phi_W + phi_b)
    gemm_kernel<2, false, 0><<<dim3(32, 4, 1), 256>>>(
        p_N, 0, phi_W, phi_b, 0, S_SM, out, nullptr, 0, 1.f, 2048, 256, 256, 256);
}

// round 4
// speedup vs baseline: 3.7614x; 1.4191x over previous
#include <cuda_runtime.h>
#include <cuda_bf16.h>
#include <math.h>

#define BB 2
#define LQ 1024
#define CC 256
#define LK 4096
#define NCH 2
#define NHD 8
#define HD 32
#define EPSV 1e-8f

// ---------------- scratch (device globals; no allocation) ----------------
__device__ float g_partial[BB * 16 * CC];
__device__ float g_smean[BB * CC];
__device__ float g_sproj[BB * CC];
__device__ float g_h[BB * LK * CC];          // fp32 (feeds P_hat output path)
__device__ float g_V[BB * LK];
__device__ float g_Wcomb[CC * CC];
__device__ float g_bcomb[CC];
__device__ __nv_bfloat16 g_Qinb[BB * LQ * 2 * CC];
__device__ __nv_bfloat16 g_hqb[BB * LQ * CC];
__device__ __nv_bfloat16 g_fqT[BB * LK * CC];   // f_q transposed, bf16 [b][Lk][C]
__device__ __nv_bfloat16 g_qb[BB * LQ * CC];    // q (scaled) bf16
__device__ __nv_bfloat16 g_kb[BB * LK * CC];    // k bf16
__device__ __nv_bfloat16 g_vT[BB * CC * LK];    // v bf16 transposed [b][C][Lk]
__device__ __nv_bfloat16 g_attb[BB * LQ * CC];  // attention out bf16
__device__ __nv_bfloat16 g_Nb[BB * LQ * CC];    // N bf16

__device__ __forceinline__ unsigned packbf(float x, float y) {
    __nv_bfloat162 h = __floats2bfloat162_rn(x, y);
    return *(unsigned*)&h;
}

// ---------------- mean of S_SM over Lq ----------------
__global__ void mean_partial_kernel(const float* __restrict__ S_SM) {
    int b = blockIdx.y, seg = blockIdx.x, c = threadIdx.x;
    const float* base = S_SM + ((size_t)b * LQ + (size_t)seg * 64) * CC + c;
    float acc = 0.f;
    #pragma unroll 8
    for (int l = 0; l < 64; l++) acc += base[(size_t)l * CC];
    g_partial[(b * 16 + seg) * CC + c] = acc;
}

__global__ void mean_final_kernel() {
    int i = blockIdx.x * blockDim.x + threadIdx.x;
    int b = i / CC, c = i % CC;
    float acc = 0.f;
    #pragma unroll
    for (int s = 0; s < 16; s++) acc += g_partial[(b * 16 + s) * CC + c];
    g_smean[i] = acc * (1.0f / LQ);
}

__global__ void sproj_kernel(const float* __restrict__ qp_W1,
                             const float* __restrict__ qp_b1) {
    int b = blockIdx.x, n = threadIdx.x;
    float acc = qp_b1[n];
    for (int c = 0; c < CC; c++) acc += g_smean[b * CC + c] * qp_W1[(size_t)c * CC + n];
    g_sproj[b * CC + n] = acc;
}

// ---------------- Wcomb = phiQ_W2 @ Wq ; bcomb = phiQ_b2 @ Wq + bq ----------------
__global__ void wcomb_kernel(const float* __restrict__ W2, const float* __restrict__ Wq,
                             const float* __restrict__ b2, const float* __restrict__ bq) {
    int k = blockIdx.x, n = threadIdx.x;
    float acc = 0.f;
    for (int c = 0; c < CC; c++) acc += W2[(size_t)k * CC + c] * Wq[(size_t)c * CC + n];
    g_Wcomb[(size_t)k * CC + n] = acc;
    if (k == 0) {
        float bacc = bq[n];
        for (int c = 0; c < CC; c++) bacc += b2[c] * Wq[(size_t)c * CC + n];
        g_bcomb[n] = bacc;
    }
}

// ---------------- Qin = concat(S_QP, S_SM) -> bf16 ----------------
__global__ void concat_bf16_kernel(const float* __restrict__ S_QP,
                                   const float* __restrict__ S_SM) {
    int i = blockIdx.x * blockDim.x + threadIdx.x;
    const int rowp = CC;
    const int total = BB * LQ * rowp;
    if (i >= total) return;
    int row = i / rowp, p = i % rowp;
    float2 v;
    if (p < CC / 2) v = ((const float2*)S_QP)[(size_t)row * (CC / 2) + p];
    else            v = ((const float2*)S_SM)[(size_t)row * (CC / 2) + p - CC / 2];
    ((unsigned*)g_Qinb)[i] = packbf(v.x, v.y);
}

// ---------------- f_q [b][C][Lk] fp32 -> fqT [b][Lk][C] bf16 ----------------
__global__ void transpose_fq_kernel(const float* __restrict__ f_q) {
    __shared__ float tile[32][33];
    int b = blockIdx.z;
    int l0 = blockIdx.x * 32, c0 = blockIdx.y * 32;
    int tx = threadIdx.x & 31, ty = threadIdx.x >> 5;  // 32 x 8
    const float* src = f_q + ((size_t)b * CC + c0) * LK + l0;
    #pragma unroll
    for (int j = 0; j < 4; j++) tile[ty + 8 * j][tx] = src[(size_t)(ty + 8 * j) * LK + tx];
    __syncthreads();
    unsigned* dst = (unsigned*)(g_fqT + ((size_t)b * LK + l0) * CC + c0);
    #pragma unroll
    for (int it = 0; it < 2; it++) {
        int i = threadIdx.x + it * 256;
        int r = i >> 4, p = i & 15;
        dst[(size_t)r * (CC / 2) + p] = packbf(tile[2 * p][r], tile[2 * p + 1][r]);
    }
}

// ---------------- fp32 SIMT GEMM (h path only; precision-critical) ----------------
// h[m,n] = relu( sum_k f_q[k,m]*W[k,n] + bias[b][n] ), A is [K,M] row-major (trans)
__global__ __launch_bounds__(256)
void gemm_fp32_h_kernel(const float* __restrict__ A, long strideA,
                        const float* __restrict__ W,
                        const float* __restrict__ bias,
                        float* __restrict__ Cout, long strideC,
                        int M, int N, int K, int lda) {
    const int BM = 64, BN = 64, BK = 16;
    __shared__ __align__(16) float As[BK][BM];
    __shared__ __align__(16) float Bs[BK][BN];

    int bz = blockIdx.z;
    A += (size_t)bz * strideA;
    Cout += (size_t)bz * strideC;
    const float* biasP = bias + (size_t)bz * CC;

    int m0 = blockIdx.x * BM, n0 = blockIdx.y * BN;
    int t = threadIdx.x;
    int tx = t % 16, ty = t / 16;

    float acc[4][4];
    #pragma unroll
    for (int i = 0; i < 4; i++)
        #pragma unroll
        for (int j = 0; j < 4; j++) acc[i][j] = 0.f;

    for (int k0 = 0; k0 < K; k0 += BK) {
        {
            int kk = t / 16, mm4 = (t % 16) * 4;
            float4 av = *(const float4*)&A[(size_t)(k0 + kk) * lda + m0 + mm4];
            *(float4*)&As[kk][mm4] = av;
        }
        {
            int kk = t / 16, nn4 = (t % 16) * 4;
            *(float4*)&Bs[kk][nn4] = *(const float4*)&W[(size_t)(k0 + kk) * N + n0 + nn4];
        }
        __syncthreads();
        #pragma unroll
        for (int kk = 0; kk < BK; kk++) {
            float4 a4 = *(const float4*)&As[kk][ty * 4];
            float4 b4 = *(const float4*)&Bs[kk][tx * 4];
            float a[4] = {a4.x, a4.y, a4.z, a4.w};
            float b[4] = {b4.x, b4.y, b4.z, b4.w};
            #pragma unroll
            for (int i = 0; i < 4; i++)
                #pragma unroll
                for (int j = 0; j < 4; j++) acc[i][j] += a[i] * b[j];
        }
        __syncthreads();
    }

    #pragma unroll
    for (int i = 0; i < 4; i++) {
        int m = m0 + ty * 4 + i;
        #pragma unroll
        for (int j = 0; j < 4; j++) {
            int n = n0 + tx * 4 + j;
            float v = acc[i][j] + biasP[n];
            Cout[(size_t)m * N + n] = fmaxf(v, 0.f);
        }
    }
}

// ---------------- bf16 HMMA helpers ----------------
__device__ __forceinline__ void mma16816(float* c, const unsigned* a, const unsigned* b) {
    asm volatile(
        "mma.sync.aligned.m16n8k16.row.col.f32.bf16.bf16.f32 "
        "{%0,%1,%2,%3}, {%4,%5,%6,%7}, {%8,%9}, {%0,%1,%2,%3};\n"
        : "+f"(c[0]), "+f"(c[1]), "+f"(c[2]), "+f"(c[3])
        : "r"(a[0]), "r"(a[1]), "r"(a[2]), "r"(a[3]), "r"(b[0]), "r"(b[1]));
}

// ---------------- bf16 tensor-core GEMM ----------------
// EPI: 0 bias, 1 bias+relu, 2 Dsub - (acc+bias)
// OUTMODE: 0 fp32 row-major, 1 bf16 row-major (*outScale), 2 bf16 transposed [N][M]
template <int EPI, int OUTMODE>
__global__ __launch_bounds__(128)
void hgemm_kernel(const __nv_bfloat16* __restrict__ A, long strideA,
                  const float* __restrict__ W, int ldw,
                  const float* __restrict__ bias, int biasStride,
                  const float* __restrict__ Dsub,
                  float* __restrict__ CoutF, __nv_bfloat16* __restrict__ CoutB,
                  long strideC, float outScale,
                  int M, int N, int K) {
    __shared__ __align__(16) __nv_bfloat16 As[64][40];
    __shared__ __align__(16) __nv_bfloat16 Bs[64][40];

    int bz = blockIdx.z;
    A += (size_t)bz * strideA;
    if (OUTMODE == 0) CoutF += (size_t)bz * strideC;
    else              CoutB += (size_t)bz * strideC;
    const float* biasP = bias + (size_t)bz * biasStride;

    int m0 = blockIdx.x * 64, n0 = blockIdx.y * 64;
    int tid = threadIdx.x, warp = tid >> 5, lane = tid & 31;
    int wm = warp & 1, wn = warp >> 1;
    int qrow = lane >> 2, qc2 = (lane & 3) * 2;

    float c[2][4][4];
    #pragma unroll
    for (int i = 0; i < 2; i++)
        #pragma unroll
        for (int j = 0; j < 4; j++)
            #pragma unroll
            for (int r = 0; r < 4; r++) c[i][j][r] = 0.f;

    for (int k0 = 0; k0 < K; k0 += 32) {
        #pragma unroll
        for (int it = 0; it < 2; it++) {
            int i = tid + it * 128;
            int row = i >> 2, seg = i & 3;
            *(uint4*)&As[row][seg * 8] =
                *(const uint4*)(A + (size_t)(m0 + row) * K + k0 + seg * 8);
        }
        #pragma unroll
        for (int it = 0; it < 4; it++) {
            int i = tid + it * 128;
            int kk = i >> 4, n4 = (i & 15) * 4;
            float4 wv = *(const float4*)(W + (size_t)(k0 + kk) * ldw + n0 + n4);
            Bs[n4 + 0][kk] = __float2bfloat16_rn(wv.x);
            Bs[n4 + 1][kk] = __float2bfloat16_rn(wv.y);
            Bs[n4 + 2][kk] = __float2bfloat16_rn(wv.z);
            Bs[n4 + 3][kk] = __float2bfloat16_rn(wv.w);
        }
        __syncthreads();
        #pragma unroll
        for (int kk = 0; kk < 32; kk += 16) {
            unsigned a[2][4], bfr[4][2];
            #pragma unroll
            for (int i = 0; i < 2; i++) {
                int r = wm * 32 + i * 16 + qrow;
                a[i][0] = *(const unsigned*)&As[r][kk + qc2];
                a[i][1] = *(const unsigned*)&As[r + 8][kk + qc2];
                a[i][2] = *(const unsigned*)&As[r][kk + qc2 + 8];
                a[i][3] = *(const unsigned*)&As[r + 8][kk + qc2 + 8];
            }
            #pragma unroll
            for (int j = 0; j < 4; j++) {
                int n = wn * 32 + j * 8 + qrow;
                bfr[j][0] = *(const unsigned*)&Bs[n][kk + qc2];
                bfr[j][1] = *(const unsigned*)&Bs[n][kk + qc2 + 8];
            }
            #pragma unroll
            for (int i = 0; i < 2; i++)
                #pragma unroll
                for (int j = 0; j < 4; j++) mma16816(c[i][j], a[i], bfr[j]);
        }
        __syncthreads();
    }

    #pragma unroll
    for (int i = 0; i < 2; i++) {
        #pragma unroll
        for (int j = 0; j < 4; j++) {
            int m = m0 + wm * 32 + i * 16 + qrow;
            int n = n0 + wn * 32 + j * 8 + qc2;
            float b0 = biasP[n], b1 = biasP[n + 1];
            float v0 = c[i][j][0] + b0, v1 = c[i][j][1] + b1;
            float v2 = c[i][j][2] + b0, v3 = c[i][j][3] + b1;
            if (EPI == 1) {
                v0 = fmaxf(v0, 0.f); v1 = fmaxf(v1, 0.f);
                v2 = fmaxf(v2, 0.f); v3 = fmaxf(v3, 0.f);
            }
            if (EPI == 2) {
                v0 = Dsub[(size_t)m * N + n] - v0;
                v1 = Dsub[(size_t)m * N + n + 1] - v1;
                v2 = Dsub[(size_t)(m + 8) * N + n] - v2;
                v3 = Dsub[(size_t)(m + 8) * N + n + 1] - v3;
            }
            if (OUTMODE == 0) {
                *(float2*)&CoutF[(size_t)m * N + n] = make_float2(v0, v1);
                *(float2*)&CoutF[(size_t)(m + 8) * N + n] = make_float2(v2, v3);
            } else if (OUTMODE == 1) {
                *(unsigned*)&CoutB[(size_t)m * N + n] = packbf(v0 * outScale, v1 * outScale);
                *(unsigned*)&CoutB[(size_t)(m + 8) * N + n] = packbf(v2 * outScale, v3 * outScale);
            } else {
                CoutB[(size_t)n * M + m] = __float2bfloat16_rn(v0);
                CoutB[(size_t)(n + 1) * M + m] = __float2bfloat16_rn(v1);
                CoutB[(size_t)n * M + m + 8] = __float2bfloat16_rn(v2);
                CoutB[(size_t)(n + 1) * M + m + 8] = __float2bfloat16_rn(v3);
            }
        }
    }
}

// ---------------- P_hat + entropy + V (warp per pixel) ----------------
__device__ __forceinline__ float ent2(float x0, float x1) {
    float d = x0 - x1;
    float p0 = 1.f / (1.f + expf(-d));
    float p1 = 1.f / (1.f + expf(d));
    p0 = fmaxf(p0, EPSV);
    p1 = fmaxf(p1, EPSV);
    return -(p0 * logf(p0) + p1 * logf(p1));
}

__global__ void phat_kernel(const float* __restrict__ P,
                            const float* __restrict__ qp_W2,
                            const float* __restrict__ qp_b2,
                            float* __restrict__ out) {
    int gwarp = (blockIdx.x * blockDim.x + threadIdx.x) >> 5;
    int lane = threadIdx.x & 31;
    if (gwarp >= BB * LK) return;
    int b = gwarp / LK, pix = gwarp % LK;
    const float* hrow = g_h + (size_t)gwarp * CC;
    float a0 = 0.f, a1 = 0.f;
    #pragma unroll
    for (int i = lane; i < CC; i += 32) {
        float hv = hrow[i];
        a0 += hv * qp_W2[i * 2 + 0];
        a1 += hv * qp_W2[i * 2 + 1];
    }
    #pragma unroll
    for (int o = 16; o; o >>= 1) {
        a0 += __shfl_down_sync(0xffffffffu, a0, o);
        a1 += __shfl_down_sync(0xffffffffu, a1, o);
    }
    if (lane == 0) {
        float ph0 = a0 + qp_b2[0];
        float ph1 = a1 + qp_b2[1];
        float* phat = out + (size_t)BB * LQ * CC;
        phat[((size_t)b * NCH + 0) * LK + pix] = ph0;
        phat[((size_t)b * NCH + 1) * LK + pix] = ph1;
        float p0 = P[((size_t)b * NCH + 0) * LK + pix];
        float p1 = P[((size_t)b * NCH + 1) * LK + pix];
        float Vv = ent2(ph0, ph1) - ent2(p0, p1);
        float* vout = out + (size_t)BB * LQ * CC + (size_t)BB * NCH * LK;
        vout[(size_t)b * LK + pix] = Vv;
        g_V[b * LK + pix] = Vv;
    }
}

// ---------------- bf16 tensor-core attention ----------------
// grid (LQ/64, NH, B), block 128 (4 warps x 16 query rows each)
// Logits are bounded (|q.k*scale| < ~0.1, |V| <= ln2): exp without max is safe.
__global__ __launch_bounds__(128)
void attn_mma_kernel(const __nv_bfloat16* __restrict__ qb,
                     const __nv_bfloat16* __restrict__ kb,
                     const __nv_bfloat16* __restrict__ vT,
                     __nv_bfloat16* __restrict__ attout) {
    __shared__ __align__(16) __nv_bfloat16 Ks[64][40];
    __shared__ __align__(16) __nv_bfloat16 Vt[32][72];
    __shared__ float bias_s[64];

    int qt = blockIdx.x, h = blockIdx.y, b = blockIdx.z;
    int tid = threadIdx.x, warp = tid >> 5, lane = tid & 31;
    int qr = qt * 64 + warp * 16 + (lane >> 2);
    int qc = (lane & 3) * 2;

    unsigned aq[2][4];
    const __nv_bfloat16* qbase = qb + ((size_t)(b * LQ) + qr) * CC + h * HD;
    #pragma unroll
    for (int ks = 0; ks < 2; ks++) {
        aq[ks][0] = *(const unsigned*)(qbase + ks * 16 + qc);
        aq[ks][1] = *(const unsigned*)(qbase + (size_t)8 * CC + ks * 16 + qc);
        aq[ks][2] = *(const unsigned*)(qbase + ks * 16 + qc + 8);
        aq[ks][3] = *(const unsigned*)(qbase + (size_t)8 * CC + ks * 16 + qc + 8);
    }

    float o[4][4];
    #pragma unroll
    for (int i = 0; i < 4; i++)
        #pragma unroll
        for (int j = 0; j < 4; j++) o[i][j] = 0.f;
    float l0 = 0.f, l1 = 0.f;

    for (int kb0 = 0; kb0 < LK; kb0 += 64) {
        __syncthreads();
        #pragma unroll
        for (int it = 0; it < 4; it++) {
            int i = tid + it * 128;
            int row = i >> 3, j = i & 7;
            *(uint2*)&Ks[row][j * 4] =
                *(const uint2*)(kb + ((size_t)(b * LK) + kb0 + row) * CC + h * HD + j * 4);
        }
        #pragma unroll
        for (int it = 0; it < 4; it++) {
            int i = tid + it * 128;
            int row = i >> 4, j = i & 15;
            *(uint2*)&Vt[row][j * 4] =
                *(const uint2*)(vT + ((size_t)b * CC + h * HD + row) * LK + kb0 + j * 4);
        }
        if (tid < 64) bias_s[tid] = g_V[b * LK + kb0 + tid];
        __syncthreads();

        float c[8][4];
        #pragma unroll
        for (int nt = 0; nt < 8; nt++) {
            c[nt][0] = c[nt][1] = c[nt][2] = c[nt][3] = 0.f;
            int n = nt * 8 + (lane >> 2);
            #pragma unroll
            for (int ks = 0; ks < 2; ks++) {
                unsigned bf[2];
                int k0 = ks * 16 + qc;
                bf[0] = *(const unsigned*)&Ks[n][k0];
                bf[1] = *(const unsigned*)&Ks[n][k0 + 8];
                mma16816(c[nt], aq[ks], bf);
            }
        }
        #pragma unroll
        for (int nt = 0; nt < 8; nt++) {
            float b0 = bias_s[nt * 8 + qc], b1 = bias_s[nt * 8 + qc + 1];
            c[nt][0] = __expf(c[nt][0] + b0);
            c[nt][1] = __expf(c[nt][1] + b1);
            c[nt][2] = __expf(c[nt][2] + b0);
            c[nt][3] = __expf(c[nt][3] + b1);
            l0 += c[nt][0] + c[nt][1];
            l1 += c[nt][2] + c[nt][3];
        }
        #pragma unroll
        for (int ks2 = 0; ks2 < 4; ks2++) {
            unsigned ap[4];
            ap[0] = packbf(c[2 * ks2][0], c[2 * ks2][1]);
            ap[1] = packbf(c[2 * ks2][2], c[2 * ks2][3]);
            ap[2] = packbf(c[2 * ks2 + 1][0], c[2 * ks2 + 1][1]);
            ap[3] = packbf(c[2 * ks2 + 1][2], c[2 * ks2 + 1][3]);
            #pragma unroll
            for (int nt2 = 0; nt2 < 4; nt2++) {
                int d = nt2 * 8 + (lane >> 2);
                int k0 = ks2 * 16 + qc;
                unsigned bf[2];
                bf[0] = *(const unsigned*)&Vt[d][k0];
                bf[1] = *(const unsigned*)&Vt[d][k0 + 8];
                mma16816(o[nt2], ap, bf);
            }
        }
    }

    l0 += __shfl_xor_sync(0xffffffffu, l0, 1);
    l0 += __shfl_xor_sync(0xffffffffu, l0, 2);
    l1 += __shfl_xor_sync(0xffffffffu, l1, 1);
    l1 += __shfl_xor_sync(0xffffffffu, l1, 2);
    float inv0 = 1.f / l0, inv1 = 1.f / l1;

    __nv_bfloat16* dst = attout + ((size_t)(b * LQ) + qr) * CC + h * HD;
    #pragma unroll
    for (int nt2 = 0; nt2 < 4; nt2++) {
        int c0 = nt2 * 8 + qc;
        *(unsigned*)&dst[c0] = packbf(o[nt2][0] * inv0, o[nt2][1] * inv0);
        *(unsigned*)&dst[(size_t)8 * CC + c0] = packbf(o[nt2][2] * inv1, o[nt2][3] * inv1);
    }
}

// ---------------- launch ----------------
extern "C" void kernel_launch(void* const* d_in, const int* in_sizes, int n_in,
                              void* d_out, int out_size) {
    const float* S_QP   = (const float*)d_in[0];
    const float* S_SM   = (const float*)d_in[1];
    const float* f_q    = (const float*)d_in[2];
    const float* P      = (const float*)d_in[3];
    const float* qp_W1  = (const float*)d_in[4];
    const float* qp_b1  = (const float*)d_in[5];
    const float* qp_W2  = (const float*)d_in[6];
    const float* qp_b2  = (const float*)d_in[7];
    const float* phiQ_W1 = (const float*)d_in[8];
    const float* phiQ_b1 = (const float*)d_in[9];
    const float* phiQ_W2 = (const float*)d_in[10];
    const float* phiQ_b2 = (const float*)d_in[11];
    const float* Wq = (const float*)d_in[12];
    const float* bq = (const float*)d_in[13];
    const float* Wk = (const float*)d_in[14];
    const float* bk = (const float*)d_in[15];
    const float* Wv = (const float*)d_in[16];
    const float* bv = (const float*)d_in[17];
    const float* Wo = (const float*)d_in[18];
    const float* bo = (const float*)d_in[19];
    const float* phi_W = (const float*)d_in[20];
    const float* phi_b = (const float*)d_in[21];
    float* out = (float*)d_out;

    float *p_h, *p_sproj, *p_Wcomb, *p_bcomb;
    __nv_bfloat16 *p_Qinb, *p_hqb, *p_fqT, *p_qb, *p_kb, *p_vT, *p_attb, *p_Nb;
    cudaGetSymbolAddress((void**)&p_h, g_h);
    cudaGetSymbolAddress((void**)&p_sproj, g_sproj);
    cudaGetSymbolAddress((void**)&p_Wcomb, g_Wcomb);
    cudaGetSymbolAddress((void**)&p_bcomb, g_bcomb);
    cudaGetSymbolAddress((void**)&p_Qinb, g_Qinb);
    cudaGetSymbolAddress((void**)&p_hqb, g_hqb);
    cudaGetSymbolAddress((void**)&p_fqT, g_fqT);
    cudaGetSymbolAddress((void**)&p_qb, g_qb);
    cudaGetSymbolAddress((void**)&p_kb, g_kb);
    cudaGetSymbolAddress((void**)&p_vT, g_vT);
    cudaGetSymbolAddress((void**)&p_attb, g_attb);
    cudaGetSymbolAddress((void**)&p_Nb, g_Nb);

    const float attnScale = 0.17677669529663687f;  // 1/sqrt(32)

    // prototype mean + folded bias + composite weight
    mean_partial_kernel<<<dim3(16, BB), 256>>>(S_SM);
    mean_final_kernel<<<2, 256>>>();
    sproj_kernel<<<BB, 256>>>(qp_W1, qp_b1);
    wcomb_kernel<<<CC, CC>>>(phiQ_W2, Wq, phiQ_b2, bq);

    // bf16 staging
    concat_bf16_kernel<<<(BB * LQ * CC + 255) / 256, 256>>>(S_QP, S_SM);
    transpose_fq_kernel<<<dim3(LK / 32, CC / 32, BB), 256>>>(f_q);

    // hq = relu(Qin @ phiQ_W1 + b1) -> bf16
    hgemm_kernel<1, 1><<<dim3(32, 4, 1), 128>>>(
        p_Qinb, 0, phiQ_W1, CC, phiQ_b1, 0, nullptr,
        nullptr, p_hqb, 0, 1.f, 2048, 256, 512);
    // q = (hq @ Wcomb + bcomb) * scale -> bf16
    hgemm_kernel<0, 1><<<dim3(32, 4, 1), 128>>>(
        p_hqb, 0, p_Wcomb, CC, p_bcomb, 0, nullptr,
        nullptr, p_qb, 0, attnScale, 2048, 256, 256);
    // k = fqT @ Wk + bk -> bf16
    hgemm_kernel<0, 1><<<dim3(64, 4, BB), 128>>>(
        p_fqT, (long)LK * CC, Wk, CC, bk, 0, nullptr,
        nullptr, p_kb, (long)LK * CC, 1.f, 4096, 256, 256);
    // v = fqT @ Wv + bv -> bf16 transposed [C][Lk]
    hgemm_kernel<0, 2><<<dim3(64, 4, BB), 128>>>(
        p_fqT, (long)LK * CC, Wv, CC, bv, 0, nullptr,
        nullptr, p_vT, (long)CC * LK, 1.f, 4096, 256, 256);
    // h = relu(f_q^T @ qp_W1[C:] + sproj[b]) -> fp32 SIMT (precision-critical: P_hat)
    gemm_fp32_h_kernel<<<dim3(64, 4, BB), 256>>>(
        f_q, (long)CC * LK, qp_W1 + (size_t)CC * CC, p_sproj,
        p_h, (long)LK * CC, 4096, 256, 256, LK);

    // P_hat + entropy + V
    phat_kernel<<<(BB * LK) / 8, 256>>>(P, qp_W2, qp_b2, out);

    // attention (bf16 HMMA) -> bf16
    attn_mma_kernel<<<dim3(LQ / 64, NHD, BB), 128>>>(p_qb, p_kb, p_vT, p_attb);

    // N = att @ Wo + bo -> bf16
    hgemm_kernel<0, 1><<<dim3(32, 4, 1), 128>>>(
        p_attb, 0, Wo, CC, bo, 0, nullptr,
        nullptr, p_Nb, 0, 1.f, 2048, 256, 256);
    // S_IC = S_SM - (N @ phi_W + phi_b) -> fp32 out
    hgemm_kernel<2, 0><<<dim3(32, 4, 1), 128>>>(
        p_Nb, 0, phi_W, CC, phi_b, 0, S_SM,
        out, nullptr, 0, 1.f, 2048, 256, 256);
}